// round 1
// baseline (speedup 1.0000x reference)
#include <cuda_runtime.h>
#include <cstdint>

// Problem constants (fixed by reference setup)
#define Bq 32
#define Dd 512
#define Tt 256
#define Nq 8192    // B*T queries
#define Kc 8192    // codebook entries

// GEMM tiling
#define BM 128
#define BN 128
#define BK 16
#define CS 8                        // code-dimension split across blocks
#define CODES_PER_BLK (Kc / CS)     // 1024

// Scratch (no allocations allowed -> device globals)
__device__ float              g_c2[Kc];
__device__ unsigned long long g_min[Nq];
__device__ int                g_cnt[Kc];
__device__ int                g_idx[Nq];
__device__ float              g_loss;

// ---------------------------------------------------------------------------
// Init scratch
// ---------------------------------------------------------------------------
__global__ void k_init() {
    int i = blockIdx.x * blockDim.x + threadIdx.x;
    if (i < Nq) g_min[i] = 0xFFFFFFFFFFFFFFFFULL;
    if (i < Kc) g_cnt[i] = 0;
    if (i == 0) g_loss = 0.0f;
}

// ---------------------------------------------------------------------------
// Codebook row norms: one warp per code
// ---------------------------------------------------------------------------
__global__ void k_norms(const float* __restrict__ cb) {
    int warp = threadIdx.x >> 5;
    int lane = threadIdx.x & 31;
    int code = blockIdx.x * 8 + warp;
    const float* row = cb + (size_t)code * Dd;
    float s = 0.0f;
#pragma unroll
    for (int p = 0; p < 4; p++) {
        float4 v = *(const float4*)(row + lane * 4 + p * 128);
        s += v.x * v.x + v.y * v.y + v.z * v.z + v.w * v.w;
    }
#pragma unroll
    for (int off = 16; off; off >>= 1) s += __shfl_down_sync(0xFFFFFFFFu, s, off);
    if (lane == 0) g_c2[code] = s;
}

// ---------------------------------------------------------------------------
// Fused fp32 GEMM + argmin.
// grid = (Nq/BM = 64, CS = 8). Each block: 128 queries x 1024 codes, K=512.
// dist = ||c||^2 - 2*(z . c)   (query norm dropped: constant per row)
// ---------------------------------------------------------------------------
__device__ __forceinline__ unsigned f_ord(float f) {
    unsigned u = __float_as_uint(f);
    return (u & 0x80000000u) ? ~u : (u | 0x80000000u);
}

__global__ __launch_bounds__(256, 2) void k_argmin(const float* __restrict__ z,
                                                   const float* __restrict__ cb) {
    __shared__ float As[BK][BM];
    __shared__ float Bs[BK][BN];

    const int tid = threadIdx.x;
    const int tx = tid & 15;       // code-dim thread coord
    const int ty = tid >> 4;       // query-dim thread coord

    const int n0 = blockIdx.x * BM;          // query base (BM divides T -> b const)
    const int b  = n0 / Tt;
    const int t0 = n0 % Tt;
    const float* zb = z + (size_t)b * Dd * Tt + t0;   // z_e[b, :, t0...]
    const int cbase = blockIdx.y * CODES_PER_BLK;

    // load lane mapping
    const int la_k = tid >> 4;         // 0..15
    const int la_m = (tid & 15) * 8;   // 0..120
    const int lb_n = tid >> 1;         // 0..127
    const int lb_k = (tid & 1) * 8;    // 0 or 8

    float bestd[8];
    int   besti[8];
#pragma unroll
    for (int i = 0; i < 8; i++) { bestd[i] = 3.4e38f; besti[i] = 0; }

    for (int ct = 0; ct < CODES_PER_BLK / BN; ct++) {
        const int c0 = cbase + ct * BN;
        float acc[8][8];
#pragma unroll
        for (int i = 0; i < 8; i++)
#pragma unroll
            for (int j = 0; j < 8; j++) acc[i][j] = 0.0f;

        for (int k0 = 0; k0 < Dd; k0 += BK) {
            // issue global loads early
            float4 a0 = *(const float4*)(zb + (size_t)(k0 + la_k) * Tt + la_m);
            float4 a1 = *(const float4*)(zb + (size_t)(k0 + la_k) * Tt + la_m + 4);
            float4 b0 = *(const float4*)(cb + (size_t)(c0 + lb_n) * Dd + k0 + lb_k);
            float4 b1 = *(const float4*)(cb + (size_t)(c0 + lb_n) * Dd + k0 + lb_k + 4);

            __syncthreads();   // previous tile compute done
            *(float4*)&As[la_k][la_m]     = a0;
            *(float4*)&As[la_k][la_m + 4] = a1;
            Bs[lb_k + 0][lb_n] = b0.x; Bs[lb_k + 1][lb_n] = b0.y;
            Bs[lb_k + 2][lb_n] = b0.z; Bs[lb_k + 3][lb_n] = b0.w;
            Bs[lb_k + 4][lb_n] = b1.x; Bs[lb_k + 5][lb_n] = b1.y;
            Bs[lb_k + 6][lb_n] = b1.z; Bs[lb_k + 7][lb_n] = b1.w;
            __syncthreads();

#pragma unroll
            for (int kk = 0; kk < BK; kk++) {
                float4 fa0 = *(const float4*)&As[kk][ty * 8];
                float4 fa1 = *(const float4*)&As[kk][ty * 8 + 4];
                float4 fb0 = *(const float4*)&Bs[kk][tx * 8];
                float4 fb1 = *(const float4*)&Bs[kk][tx * 8 + 4];
                float av[8] = {fa0.x, fa0.y, fa0.z, fa0.w, fa1.x, fa1.y, fa1.z, fa1.w};
                float bv[8] = {fb0.x, fb0.y, fb0.z, fb0.w, fb1.x, fb1.y, fb1.z, fb1.w};
#pragma unroll
                for (int i = 0; i < 8; i++)
#pragma unroll
                    for (int j = 0; j < 8; j++)
                        acc[i][j] = fmaf(av[i], bv[j], acc[i][j]);
            }
        }

        // fold this code tile into running argmin (codes ascending -> '<' keeps first)
#pragma unroll
        for (int j = 0; j < 8; j++) {
            int c = c0 + tx * 8 + j;
            float c2 = g_c2[c];
#pragma unroll
            for (int i = 0; i < 8; i++) {
                float d = c2 - 2.0f * acc[i][j];
                if (d < bestd[i]) { bestd[i] = d; besti[i] = c; }
            }
        }
    }

    // global reduction: packed (ordered dist | idx); min -> min dist, tie -> min idx
#pragma unroll
    for (int i = 0; i < 8; i++) {
        unsigned long long p =
            ((unsigned long long)f_ord(bestd[i]) << 32) | (unsigned)besti[i];
        atomicMin(&g_min[n0 + ty * 8 + i], p);
    }
}

// ---------------------------------------------------------------------------
// Extract indices + histogram
// ---------------------------------------------------------------------------
__global__ void k_post() {
    int n = blockIdx.x * 256 + threadIdx.x;
    int idx = (int)(g_min[n] & 0xFFFFFFFFULL);
    g_idx[n] = idx;
    atomicAdd(&g_cnt[idx], 1);
}

// ---------------------------------------------------------------------------
// Gather z_q into (b, d, t) layout + commitment-loss partial sums
// grid = B*D blocks, 256 threads = t
// ---------------------------------------------------------------------------
__global__ void k_gather(const float* __restrict__ z, const float* __restrict__ cb,
                         float* __restrict__ out) {
    int bd = blockIdx.x;          // b*512 + d
    int b  = bd >> 9;
    int d  = bd & 511;
    int t  = threadIdx.x;
    int n  = b * Tt + t;
    int idx = g_idx[n];
    size_t o = (size_t)bd * Tt + t;

    float c  = cb[(size_t)idx * Dd + d];
    float zv = z[o];
    out[o] = c;                    // straight-through value == z_q

    float diff = c - zv;
    float s = diff * diff;
#pragma unroll
    for (int off = 16; off; off >>= 1) s += __shfl_down_sync(0xFFFFFFFFu, s, off);
    __shared__ float ws[8];
    if ((t & 31) == 0) ws[t >> 5] = s;
    __syncthreads();
    if (t < 8) {
        float v = ws[t];
#pragma unroll
        for (int off = 4; off; off >>= 1) v += __shfl_down_sync(0xFFu, v, off);
        if (t == 0) atomicAdd(&g_loss, v);
    }
}

// ---------------------------------------------------------------------------
// Finalize: vq_loss + perplexity
// ---------------------------------------------------------------------------
__global__ void k_final(float* __restrict__ out) {
    int t = threadIdx.x;
    float local = 0.0f;
    for (int k = t; k < Kc; k += 256) {
        float p = (float)g_cnt[k] * (1.0f / (float)Nq);
        local += p * logf(p + 1e-10f);
    }
#pragma unroll
    for (int off = 16; off; off >>= 1) local += __shfl_down_sync(0xFFFFFFFFu, local, off);
    __shared__ float ws[8];
    if ((t & 31) == 0) ws[t >> 5] = local;
    __syncthreads();
    if (t == 0) {
        float tot = 0.0f;
#pragma unroll
        for (int i = 0; i < 8; i++) tot += ws[i];
        size_t base = (size_t)Bq * Dd * Tt;
        out[base]     = 0.25f * g_loss / (float)((size_t)Nq * Dd);  // ALPHA*BETA*mean
        out[base + 1] = expf(-tot);
    }
}

// ---------------------------------------------------------------------------
extern "C" void kernel_launch(void* const* d_in, const int* in_sizes, int n_in,
                              void* d_out, int out_size) {
    const float* z  = (const float*)d_in[0];   // z_e (32, 512, 256) f32
    const float* cb = (const float*)d_in[1];   // codebook (8192, 512) f32
    float* out = (float*)d_out;
    (void)in_sizes; (void)n_in; (void)out_size;

    k_init<<<32, 256>>>();
    k_norms<<<Kc / 8, 256>>>(cb);
    dim3 grid(Nq / BM, CS);
    k_argmin<<<grid, 256>>>(z, cb);
    k_post<<<Nq / 256, 256>>>();
    k_gather<<<Bq * Dd, 256>>>(z, cb, out);
    k_final<<<1, 256>>>(out);
}

// round 3
// speedup vs baseline: 4.4396x; 4.4396x over previous
#include <cuda_runtime.h>
#include <cuda_bf16.h>
#include <cuda_fp16.h>
#include <cstdint>

// Problem constants
#define Bq 32
#define Dd 512
#define Tt 256
#define Nq 8192
#define Kc 8192

// GEMM tiling
#define BM 128
#define BN 256
#define BK 32
#define STAGES 4
#define STG_A (BM * BK * 2)          // 8192 B
#define STG_B (BN * BK * 2)          // 16384 B
#define STG_BYTES (STG_A + STG_B)    // 24576 B
#define KITERS (Dd / BK)             // 16

#define MARGIN 3.0f

// Scratch (device globals; no runtime allocation allowed)
__device__ __nv_bfloat16 g_A[(size_t)Nq * Dd];    // queries bf16 [n][d]
__device__ float         g_At[(size_t)Nq * Dd];   // queries fp32 [n][d] (for exact rescore)
__device__ __nv_bfloat16 g_B[(size_t)Kc * Dd];    // codebook bf16 [c][d]
__device__ __half        g_D[(size_t)Nq * Kc];    // approx distances fp16
__device__ float         g_c2[Kc];
__device__ int           g_cnt[Kc];
__device__ int           g_idx[Nq];
__device__ float         g_loss;

// ---------------------------------------------------------------------------
// helpers
// ---------------------------------------------------------------------------
__device__ __forceinline__ uint32_t smem_u32(const void* p) {
    uint32_t a;
    asm("{ .reg .u64 t; cvta.to.shared.u64 t, %1; cvt.u32.u64 %0, t; }" : "=r"(a) : "l"(p));
    return a;
}
__device__ __forceinline__ void cp_async16(uint32_t s, const void* g) {
    asm volatile("cp.async.cg.shared.global [%0], [%1], 16;" :: "r"(s), "l"(g) : "memory");
}
#define CP_COMMIT() asm volatile("cp.async.commit_group;" ::: "memory")
#define CP_WAIT2()  asm volatile("cp.async.wait_group 2;" ::: "memory")
#define SWZ(o) ((o) ^ (((o) >> 3) & 0x70))

__device__ __forceinline__ void ldm_x4(uint32_t& r0, uint32_t& r1, uint32_t& r2, uint32_t& r3,
                                       uint32_t a) {
    asm volatile("ldmatrix.sync.aligned.m8n8.x4.shared.b16 {%0,%1,%2,%3}, [%4];"
                 : "=r"(r0), "=r"(r1), "=r"(r2), "=r"(r3) : "r"(a));
}
__device__ __forceinline__ void mma16816(float* c, const uint32_t* a, const uint32_t* b) {
    asm volatile(
        "mma.sync.aligned.m16n8k16.row.col.f32.bf16.bf16.f32 "
        "{%0,%1,%2,%3}, {%4,%5,%6,%7}, {%8,%9}, {%0,%1,%2,%3};"
        : "+f"(c[0]), "+f"(c[1]), "+f"(c[2]), "+f"(c[3])
        : "r"(a[0]), "r"(a[1]), "r"(a[2]), "r"(a[3]), "r"(b[0]), "r"(b[1]));
}
__device__ __forceinline__ unsigned f_ord(float f) {
    unsigned u = __float_as_uint(f);
    return (u & 0x80000000u) ? ~u : (u | 0x80000000u);
}

// ---------------------------------------------------------------------------
// Init
// ---------------------------------------------------------------------------
__global__ void k_init() {
    int i = blockIdx.x * blockDim.x + threadIdx.x;
    if (i < Kc) g_cnt[i] = 0;
    if (i == 0) g_loss = 0.0f;
}

// Codebook norms (exact fp32)
__global__ void k_norms(const float* __restrict__ cb) {
    int warp = threadIdx.x >> 5, lane = threadIdx.x & 31;
    int code = blockIdx.x * 8 + warp;
    const float* row = cb + (size_t)code * Dd;
    float s = 0.0f;
#pragma unroll
    for (int p = 0; p < 4; p++) {
        float4 v = *(const float4*)(row + lane * 4 + p * 128);
        s += v.x * v.x + v.y * v.y + v.z * v.z + v.w * v.w;
    }
#pragma unroll
    for (int off = 16; off; off >>= 1) s += __shfl_down_sync(0xFFFFFFFFu, s, off);
    if (lane == 0) g_c2[code] = s;
}

// ---------------------------------------------------------------------------
// A build: transpose z (b,d,t) -> [n][d] fp32 + bf16. grid (32,16), block 256
// ---------------------------------------------------------------------------
__global__ void k_convA(const float* __restrict__ z) {
    __shared__ float sm[32][257];
    int b = blockIdx.x, d0 = blockIdx.y * 32;
    int t = threadIdx.x;
    const float* zb = z + ((size_t)b * Dd + d0) * Tt;
#pragma unroll
    for (int r = 0; r < 32; r++) sm[r][t] = zb[r * Tt + t];
    __syncthreads();
    size_t row = (size_t)(b * Tt + t) * Dd + d0;
    float* pf = g_At + row;
    uint32_t hw[16];
#pragma unroll
    for (int rr = 0; rr < 16; rr++) {
        float v0 = sm[2 * rr][t], v1 = sm[2 * rr + 1][t];
        pf[2 * rr] = v0; pf[2 * rr + 1] = v1;
        __nv_bfloat16 h0 = __float2bfloat16(v0), h1 = __float2bfloat16(v1);
        hw[rr] = (uint32_t)__bfloat16_as_ushort(h0) | ((uint32_t)__bfloat16_as_ushort(h1) << 16);
    }
    uint4* pb = (uint4*)(g_A + row);
#pragma unroll
    for (int q = 0; q < 4; q++)
        pb[q] = make_uint4(hw[4 * q], hw[4 * q + 1], hw[4 * q + 2], hw[4 * q + 3]);
}

// B build: cb fp32 -> bf16. grid 8192, block 128
__global__ void k_convB(const float* __restrict__ cb) {
    int c = blockIdx.x, t = threadIdx.x;
    float4 v = *(const float4*)(cb + (size_t)c * Dd + 4 * t);
    __nv_bfloat16 h0 = __float2bfloat16(v.x), h1 = __float2bfloat16(v.y);
    __nv_bfloat16 h2 = __float2bfloat16(v.z), h3 = __float2bfloat16(v.w);
    uint2 hp = make_uint2(
        (uint32_t)__bfloat16_as_ushort(h0) | ((uint32_t)__bfloat16_as_ushort(h1) << 16),
        (uint32_t)__bfloat16_as_ushort(h2) | ((uint32_t)__bfloat16_as_ushort(h3) << 16));
    *(uint2*)(g_B + (size_t)c * Dd + 4 * t) = hp;
}

// ---------------------------------------------------------------------------
// bf16 HMMA GEMM 128x256x32, 8 warps (2x4, warp tile 64x64), 4-stage cp.async.
// Epilogue: d = ||c||^2 - 2*dot -> fp16 matrix g_D.
// grid (64, 32), block 256, dyn smem 96KB
// ---------------------------------------------------------------------------
__global__ __launch_bounds__(256, 1) void k_gemm() {
    extern __shared__ char smem[];
    const uint32_t sbase = smem_u32(smem);
    const int tid = threadIdx.x;
    const int wid = tid >> 5, lane = tid & 31;
    const int wm = (wid >> 2) * 64;       // warp m offset (0/64)
    const int wn = (wid & 3) * 64;        // warp n offset (0/64/128/192)
    const int m0 = blockIdx.x * BM, n0 = blockIdx.y * BN;

    const __nv_bfloat16* gA = g_A;
    const __nv_bfloat16* gB = g_B;

    float acc[4][8][4];
#pragma unroll
    for (int i = 0; i < 4; i++)
#pragma unroll
        for (int j = 0; j < 8; j++)
#pragma unroll
            for (int k = 0; k < 4; k++) acc[i][j][k] = 0.0f;

    // stage loader
    auto load_stage = [&](int s, int kb) {
        uint32_t sA = sbase + s * STG_BYTES;
        uint32_t sB = sA + STG_A;
#pragma unroll
        for (int p = 0; p < 2; p++) {            // A: 512 chunks of 16B
            int j = tid + 256 * p;
            int r = j >> 2, c = j & 3;
            uint32_t off = r * 64 + c * 16;
            cp_async16(sA + SWZ(off), gA + (size_t)(m0 + r) * Dd + kb + c * 8);
        }
#pragma unroll
        for (int p = 0; p < 4; p++) {            // B: 1024 chunks
            int j = tid + 256 * p;
            int r = j >> 2, c = j & 3;
            uint32_t off = r * 64 + c * 16;
            cp_async16(sB + SWZ(off), gB + (size_t)(n0 + r) * Dd + kb + c * 8);
        }
    };

    load_stage(0, 0); CP_COMMIT();
    load_stage(1, BK); CP_COMMIT();
    load_stage(2, 2 * BK); CP_COMMIT();

    for (int i = 0; i < KITERS; i++) {
        CP_WAIT2();
        __syncthreads();
        int s = i & 3;
        if (i + 3 < KITERS) load_stage((i + 3) & 3, (i + 3) * BK);
        CP_COMMIT();

        uint32_t sA = sbase + s * STG_BYTES;
        uint32_t sB = sA + STG_A;
#pragma unroll
        for (int k16 = 0; k16 < 2; k16++) {
            const int ch = 2 * k16 + (lane >> 4);
            uint32_t af[4][4], br[4][4];
#pragma unroll
            for (int mf = 0; mf < 4; mf++) {
                int r = wm + mf * 16 + (lane & 15);
                uint32_t off = r * 64 + ch * 16;
                ldm_x4(af[mf][0], af[mf][1], af[mf][2], af[mf][3], sA + SWZ(off));
            }
#pragma unroll
            for (int nf4 = 0; nf4 < 4; nf4++) {
                int r = wn + nf4 * 16 + (lane & 15);
                uint32_t off = r * 64 + ch * 16;
                ldm_x4(br[nf4][0], br[nf4][1], br[nf4][2], br[nf4][3], sB + SWZ(off));
            }
#pragma unroll
            for (int mf = 0; mf < 4; mf++)
#pragma unroll
                for (int nf4 = 0; nf4 < 4; nf4++) {
                    uint32_t b0[2] = {br[nf4][0], br[nf4][2]};
                    uint32_t b1[2] = {br[nf4][1], br[nf4][3]};
                    mma16816(acc[mf][2 * nf4],     af[mf], b0);
                    mma16816(acc[mf][2 * nf4 + 1], af[mf], b1);
                }
        }
        __syncthreads();
    }

    // epilogue: dist = c2 - 2*dot -> fp16 store
#pragma unroll
    for (int mf = 0; mf < 4; mf++) {
#pragma unroll
        for (int nf = 0; nf < 8; nf++) {
            int m = m0 + wm + mf * 16 + (lane >> 2);
            int n = n0 + wn + nf * 8 + (lane & 3) * 2;
            float c2a = g_c2[n], c2b = g_c2[n + 1];
            float* a = acc[mf][nf];
            __half2 h0 = __float22half2_rn(make_float2(c2a - 2.0f * a[0], c2b - 2.0f * a[1]));
            __half2 h1 = __float22half2_rn(make_float2(c2a - 2.0f * a[2], c2b - 2.0f * a[3]));
            *(__half2*)(g_D + (size_t)m * Kc + n) = h0;
            *(__half2*)(g_D + (size_t)(m + 8) * Kc + n) = h1;
        }
    }
}

// ---------------------------------------------------------------------------
// Per-query scan of approx distances + exact rescore of candidates.
// grid 8192 (one block per query), block 256
// ---------------------------------------------------------------------------
__global__ __launch_bounds__(256) void k_scan(const float* __restrict__ cb) {
    const int q = blockIdx.x;
    const int tid = threadIdx.x, wid = tid >> 5, lane = tid & 31;
    const uint4* row = (const uint4*)(g_D + (size_t)q * Kc);  // 1024 x uint4 (8 halves)

    uint4 v[4];
    float lmin = 3.4e38f;
#pragma unroll
    for (int p = 0; p < 4; p++) {
        v[p] = row[tid + 256 * p];
        const uint32_t* w = (const uint32_t*)&v[p];
#pragma unroll
        for (int e = 0; e < 4; e++) {
            float2 f = __half22float2(*(const __half2*)&w[e]);
            lmin = fminf(lmin, fminf(f.x, f.y));
        }
    }
    __shared__ float wmin[8];
    __shared__ float s_m;
    __shared__ int s_cnt;
    __shared__ int s_cand[128];
    __shared__ unsigned long long s_best;
#pragma unroll
    for (int off = 16; off; off >>= 1) lmin = fminf(lmin, __shfl_down_sync(0xFFFFFFFFu, lmin, off));
    if (lane == 0) wmin[wid] = lmin;
    __syncthreads();
    if (tid == 0) {
        float m = wmin[0];
#pragma unroll
        for (int i = 1; i < 8; i++) m = fminf(m, wmin[i]);
        s_m = m; s_cnt = 0; s_best = 0xFFFFFFFFFFFFFFFFULL;
    }
    __syncthreads();
    const float thr = s_m + MARGIN;
#pragma unroll
    for (int p = 0; p < 4; p++) {
        const uint32_t* w = (const uint32_t*)&v[p];
#pragma unroll
        for (int e = 0; e < 4; e++) {
            float2 f = __half22float2(*(const __half2*)&w[e]);
            int base = (tid + 256 * p) * 8 + e * 2;
            if (f.x < thr) { int pos = atomicAdd(&s_cnt, 1); if (pos < 128) s_cand[pos] = base; }
            if (f.y < thr) { int pos = atomicAdd(&s_cnt, 1); if (pos < 128) s_cand[pos] = base + 1; }
        }
    }
    __syncthreads();
    int nc = min(s_cnt, 128);
    const float* zq = g_At + (size_t)q * Dd;
    for (int ci = wid; ci < nc; ci += 8) {
        int c = s_cand[ci];
        const float* cr = cb + (size_t)c * Dd;
        float s = 0.0f;
#pragma unroll
        for (int d = 0; d < Dd / 32; d++) s = fmaf(zq[lane + d * 32], cr[lane + d * 32], s);
#pragma unroll
        for (int off = 16; off; off >>= 1) s += __shfl_down_sync(0xFFFFFFFFu, s, off);
        if (lane == 0) {
            float dex = g_c2[c] - 2.0f * s;
            unsigned long long pk = ((unsigned long long)f_ord(dex) << 32) | (unsigned)c;
            atomicMin(&s_best, pk);
        }
    }
    __syncthreads();
    if (tid == 0) {
        int idx = (int)(s_best & 0xFFFFFFFFULL);
        g_idx[q] = idx;
        atomicAdd(&g_cnt[idx], 1);
    }
}

// ---------------------------------------------------------------------------
// Gather z_q to (b,d,t) + loss partials
// ---------------------------------------------------------------------------
__global__ void k_gather(const float* __restrict__ z, const float* __restrict__ cb,
                         float* __restrict__ out) {
    int bd = blockIdx.x;
    int b = bd >> 9, d = bd & 511;
    int t = threadIdx.x;
    int n = b * Tt + t;
    int idx = g_idx[n];
    size_t o = (size_t)bd * Tt + t;
    float c = cb[(size_t)idx * Dd + d];
    float zv = z[o];
    out[o] = c;
    float diff = c - zv;
    float s = diff * diff;
#pragma unroll
    for (int off = 16; off; off >>= 1) s += __shfl_down_sync(0xFFFFFFFFu, s, off);
    __shared__ float ws[8];
    if ((t & 31) == 0) ws[t >> 5] = s;
    __syncthreads();
    if (t < 8) {
        float v = ws[t];
#pragma unroll
        for (int off = 4; off; off >>= 1) v += __shfl_down_sync(0xFFu, v, off);
        if (t == 0) atomicAdd(&g_loss, v);
    }
}

// Finalize loss + perplexity
__global__ void k_final(float* __restrict__ out) {
    int t = threadIdx.x;
    float local = 0.0f;
    for (int k = t; k < Kc; k += 256) {
        float p = (float)g_cnt[k] * (1.0f / (float)Nq);
        local += p * logf(p + 1e-10f);
    }
#pragma unroll
    for (int off = 16; off; off >>= 1) local += __shfl_down_sync(0xFFFFFFFFu, local, off);
    __shared__ float ws[8];
    if ((t & 31) == 0) ws[t >> 5] = local;
    __syncthreads();
    if (t == 0) {
        float tot = 0.0f;
#pragma unroll
        for (int i = 0; i < 8; i++) tot += ws[i];
        size_t base = (size_t)Bq * Dd * Tt;
        out[base]     = 0.25f * g_loss / (float)((size_t)Nq * Dd);
        out[base + 1] = expf(-tot);
    }
}

// ---------------------------------------------------------------------------
extern "C" void kernel_launch(void* const* d_in, const int* in_sizes, int n_in,
                              void* d_out, int out_size) {
    const float* z  = (const float*)d_in[0];
    const float* cb = (const float*)d_in[1];
    float* out = (float*)d_out;
    (void)in_sizes; (void)n_in; (void)out_size;

    cudaFuncSetAttribute(k_gemm, cudaFuncAttributeMaxDynamicSharedMemorySize,
                         STAGES * STG_BYTES);

    k_init<<<32, 256>>>();
    k_norms<<<Kc / 8, 256>>>(cb);
    k_convA<<<dim3(32, 16), 256>>>(z);
    k_convB<<<Kc, 128>>>(cb);
    k_gemm<<<dim3(Nq / BM, Kc / BN), 256, STAGES * STG_BYTES>>>();
    k_scan<<<Nq, 256>>>(cb);
    k_gather<<<Bq * Dd, 256>>>(z, cb, out);
    k_final<<<1, 256>>>(out);
}

// round 4
// speedup vs baseline: 4.4452x; 1.0013x over previous
#include <cuda_runtime.h>
#include <cuda_bf16.h>
#include <cuda_fp16.h>
#include <cstdint>

// Problem constants
#define Bq 32
#define Dd 512
#define Tt 256
#define Nq 8192
#define Kc 8192

// GEMM tiling
#define BM 128
#define BN 256
#define BK 32
#define STAGES 4
#define STG_A (BM * BK * 2)          // 8192 B
#define STG_B (BN * BK * 2)          // 16384 B
#define STG_BYTES (STG_A + STG_B)    // 24576 B
#define KITERS (Dd / BK)             // 16

#define MARGIN 3.0f

// Scratch (device globals; no runtime allocation allowed)
__device__ __nv_bfloat16 g_A[(size_t)Nq * Dd];    // queries bf16 [n][d]
__device__ float         g_At[(size_t)Nq * Dd];   // queries fp32 [n][d] (for exact rescore)
__device__ __nv_bfloat16 g_B[(size_t)Kc * Dd];    // codebook bf16 [c][d]
__device__ __half        g_D[(size_t)Nq * Kc];    // approx distances fp16
__device__ float         g_c2[Kc];
__device__ int           g_cnt[Kc];
__device__ int           g_idx[Nq];
__device__ float         g_loss;

// ---------------------------------------------------------------------------
// helpers
// ---------------------------------------------------------------------------
__device__ __forceinline__ uint32_t smem_u32(const void* p) {
    uint32_t a;
    asm("{ .reg .u64 t; cvta.to.shared.u64 t, %1; cvt.u32.u64 %0, t; }" : "=r"(a) : "l"(p));
    return a;
}
__device__ __forceinline__ void cp_async16(uint32_t s, const void* g) {
    asm volatile("cp.async.cg.shared.global [%0], [%1], 16;" :: "r"(s), "l"(g) : "memory");
}
#define CP_COMMIT() asm volatile("cp.async.commit_group;" ::: "memory")
#define CP_WAIT2()  asm volatile("cp.async.wait_group 2;" ::: "memory")
#define SWZ(o) ((o) ^ (((o) >> 3) & 0x70))

__device__ __forceinline__ void ldm_x4(uint32_t& r0, uint32_t& r1, uint32_t& r2, uint32_t& r3,
                                       uint32_t a) {
    asm volatile("ldmatrix.sync.aligned.m8n8.x4.shared.b16 {%0,%1,%2,%3}, [%4];"
                 : "=r"(r0), "=r"(r1), "=r"(r2), "=r"(r3) : "r"(a));
}
__device__ __forceinline__ void mma16816(float* c, const uint32_t* a, const uint32_t* b) {
    asm volatile(
        "mma.sync.aligned.m16n8k16.row.col.f32.bf16.bf16.f32 "
        "{%0,%1,%2,%3}, {%4,%5,%6,%7}, {%8,%9}, {%0,%1,%2,%3};"
        : "+f"(c[0]), "+f"(c[1]), "+f"(c[2]), "+f"(c[3])
        : "r"(a[0]), "r"(a[1]), "r"(a[2]), "r"(a[3]), "r"(b[0]), "r"(b[1]));
}
__device__ __forceinline__ unsigned f_ord(float f) {
    unsigned u = __float_as_uint(f);
    return (u & 0x80000000u) ? ~u : (u | 0x80000000u);
}

// ---------------------------------------------------------------------------
// Init
// ---------------------------------------------------------------------------
__global__ void k_init() {
    int i = blockIdx.x * blockDim.x + threadIdx.x;
    if (i < Kc) g_cnt[i] = 0;
    if (i == 0) g_loss = 0.0f;
}

// Codebook norms (exact fp32)
__global__ void k_norms(const float* __restrict__ cb) {
    int warp = threadIdx.x >> 5, lane = threadIdx.x & 31;
    int code = blockIdx.x * 8 + warp;
    const float* row = cb + (size_t)code * Dd;
    float s = 0.0f;
#pragma unroll
    for (int p = 0; p < 4; p++) {
        float4 v = *(const float4*)(row + lane * 4 + p * 128);
        s += v.x * v.x + v.y * v.y + v.z * v.z + v.w * v.w;
    }
#pragma unroll
    for (int off = 16; off; off >>= 1) s += __shfl_down_sync(0xFFFFFFFFu, s, off);
    if (lane == 0) g_c2[code] = s;
}

// ---------------------------------------------------------------------------
// A build: transpose z (b,d,t) -> [n][d] fp32 + bf16. grid (32,16), block 256
// ---------------------------------------------------------------------------
__global__ void k_convA(const float* __restrict__ z) {
    __shared__ float sm[32][257];
    int b = blockIdx.x, d0 = blockIdx.y * 32;
    int t = threadIdx.x;
    const float* zb = z + ((size_t)b * Dd + d0) * Tt;
#pragma unroll
    for (int r = 0; r < 32; r++) sm[r][t] = zb[r * Tt + t];
    __syncthreads();
    size_t row = (size_t)(b * Tt + t) * Dd + d0;
    float* pf = g_At + row;
    uint32_t hw[16];
#pragma unroll
    for (int rr = 0; rr < 16; rr++) {
        float v0 = sm[2 * rr][t], v1 = sm[2 * rr + 1][t];
        pf[2 * rr] = v0; pf[2 * rr + 1] = v1;
        __nv_bfloat16 h0 = __float2bfloat16(v0), h1 = __float2bfloat16(v1);
        hw[rr] = (uint32_t)__bfloat16_as_ushort(h0) | ((uint32_t)__bfloat16_as_ushort(h1) << 16);
    }
    uint4* pb = (uint4*)(g_A + row);
#pragma unroll
    for (int q = 0; q < 4; q++)
        pb[q] = make_uint4(hw[4 * q], hw[4 * q + 1], hw[4 * q + 2], hw[4 * q + 3]);
}

// B build: cb fp32 -> bf16. grid 8192, block 128
__global__ void k_convB(const float* __restrict__ cb) {
    int c = blockIdx.x, t = threadIdx.x;
    float4 v = *(const float4*)(cb + (size_t)c * Dd + 4 * t);
    __nv_bfloat16 h0 = __float2bfloat16(v.x), h1 = __float2bfloat16(v.y);
    __nv_bfloat16 h2 = __float2bfloat16(v.z), h3 = __float2bfloat16(v.w);
    uint2 hp = make_uint2(
        (uint32_t)__bfloat16_as_ushort(h0) | ((uint32_t)__bfloat16_as_ushort(h1) << 16),
        (uint32_t)__bfloat16_as_ushort(h2) | ((uint32_t)__bfloat16_as_ushort(h3) << 16));
    *(uint2*)(g_B + (size_t)c * Dd + 4 * t) = hp;
}

// ---------------------------------------------------------------------------
// bf16 HMMA GEMM 128x256x32, 8 warps (2x4, warp tile 64x64), 4-stage cp.async.
// Epilogue: d = ||c||^2 - 2*dot -> fp16 matrix g_D.
// grid (64, 32), block 256, dyn smem 96KB
// ---------------------------------------------------------------------------
__global__ __launch_bounds__(256, 1) void k_gemm() {
    extern __shared__ char smem[];
    const uint32_t sbase = smem_u32(smem);
    const int tid = threadIdx.x;
    const int wid = tid >> 5, lane = tid & 31;
    const int wm = (wid >> 2) * 64;       // warp m offset (0/64)
    const int wn = (wid & 3) * 64;        // warp n offset (0/64/128/192)
    const int m0 = blockIdx.x * BM, n0 = blockIdx.y * BN;

    const __nv_bfloat16* gA = g_A;
    const __nv_bfloat16* gB = g_B;

    float acc[4][8][4];
#pragma unroll
    for (int i = 0; i < 4; i++)
#pragma unroll
        for (int j = 0; j < 8; j++)
#pragma unroll
            for (int k = 0; k < 4; k++) acc[i][j][k] = 0.0f;

    // stage loader
    auto load_stage = [&](int s, int kb) {
        uint32_t sA = sbase + s * STG_BYTES;
        uint32_t sB = sA + STG_A;
#pragma unroll
        for (int p = 0; p < 2; p++) {            // A: 512 chunks of 16B
            int j = tid + 256 * p;
            int r = j >> 2, c = j & 3;
            uint32_t off = r * 64 + c * 16;
            cp_async16(sA + SWZ(off), gA + (size_t)(m0 + r) * Dd + kb + c * 8);
        }
#pragma unroll
        for (int p = 0; p < 4; p++) {            // B: 1024 chunks
            int j = tid + 256 * p;
            int r = j >> 2, c = j & 3;
            uint32_t off = r * 64 + c * 16;
            cp_async16(sB + SWZ(off), gB + (size_t)(n0 + r) * Dd + kb + c * 8);
        }
    };

    load_stage(0, 0); CP_COMMIT();
    load_stage(1, BK); CP_COMMIT();
    load_stage(2, 2 * BK); CP_COMMIT();

    for (int i = 0; i < KITERS; i++) {
        CP_WAIT2();
        __syncthreads();
        int s = i & 3;
        if (i + 3 < KITERS) load_stage((i + 3) & 3, (i + 3) * BK);
        CP_COMMIT();

        uint32_t sA = sbase + s * STG_BYTES;
        uint32_t sB = sA + STG_A;
#pragma unroll
        for (int k16 = 0; k16 < 2; k16++) {
            const int ch = 2 * k16 + (lane >> 4);
            uint32_t af[4][4], br[4][4];
#pragma unroll
            for (int mf = 0; mf < 4; mf++) {
                int r = wm + mf * 16 + (lane & 15);
                uint32_t off = r * 64 + ch * 16;
                ldm_x4(af[mf][0], af[mf][1], af[mf][2], af[mf][3], sA + SWZ(off));
            }
#pragma unroll
            for (int nf4 = 0; nf4 < 4; nf4++) {
                int r = wn + nf4 * 16 + (lane & 15);
                uint32_t off = r * 64 + ch * 16;
                ldm_x4(br[nf4][0], br[nf4][1], br[nf4][2], br[nf4][3], sB + SWZ(off));
            }
#pragma unroll
            for (int mf = 0; mf < 4; mf++)
#pragma unroll
                for (int nf4 = 0; nf4 < 4; nf4++) {
                    uint32_t b0[2] = {br[nf4][0], br[nf4][2]};
                    uint32_t b1[2] = {br[nf4][1], br[nf4][3]};
                    mma16816(acc[mf][2 * nf4],     af[mf], b0);
                    mma16816(acc[mf][2 * nf4 + 1], af[mf], b1);
                }
        }
        __syncthreads();
    }

    // epilogue: dist = c2 - 2*dot -> fp16 store
#pragma unroll
    for (int mf = 0; mf < 4; mf++) {
#pragma unroll
        for (int nf = 0; nf < 8; nf++) {
            int m = m0 + wm + mf * 16 + (lane >> 2);
            int n = n0 + wn + nf * 8 + (lane & 3) * 2;
            float c2a = g_c2[n], c2b = g_c2[n + 1];
            float* a = acc[mf][nf];
            __half2 h0 = __float22half2_rn(make_float2(c2a - 2.0f * a[0], c2b - 2.0f * a[1]));
            __half2 h1 = __float22half2_rn(make_float2(c2a - 2.0f * a[2], c2b - 2.0f * a[3]));
            *(__half2*)(g_D + (size_t)m * Kc + n) = h0;
            *(__half2*)(g_D + (size_t)(m + 8) * Kc + n) = h1;
        }
    }
}

// ---------------------------------------------------------------------------
// Per-query scan of approx distances + exact rescore of candidates.
// grid 8192 (one block per query), block 256
// ---------------------------------------------------------------------------
__global__ __launch_bounds__(256) void k_scan(const float* __restrict__ cb) {
    const int q = blockIdx.x;
    const int tid = threadIdx.x, wid = tid >> 5, lane = tid & 31;
    const uint4* row = (const uint4*)(g_D + (size_t)q * Kc);  // 1024 x uint4 (8 halves)

    uint4 v[4];
    float lmin = 3.4e38f;
#pragma unroll
    for (int p = 0; p < 4; p++) {
        v[p] = row[tid + 256 * p];
        const uint32_t* w = (const uint32_t*)&v[p];
#pragma unroll
        for (int e = 0; e < 4; e++) {
            float2 f = __half22float2(*(const __half2*)&w[e]);
            lmin = fminf(lmin, fminf(f.x, f.y));
        }
    }
    __shared__ float wmin[8];
    __shared__ float s_m;
    __shared__ int s_cnt;
    __shared__ int s_cand[128];
    __shared__ unsigned long long s_best;
#pragma unroll
    for (int off = 16; off; off >>= 1) lmin = fminf(lmin, __shfl_down_sync(0xFFFFFFFFu, lmin, off));
    if (lane == 0) wmin[wid] = lmin;
    __syncthreads();
    if (tid == 0) {
        float m = wmin[0];
#pragma unroll
        for (int i = 1; i < 8; i++) m = fminf(m, wmin[i]);
        s_m = m; s_cnt = 0; s_best = 0xFFFFFFFFFFFFFFFFULL;
    }
    __syncthreads();
    const float thr = s_m + MARGIN;
#pragma unroll
    for (int p = 0; p < 4; p++) {
        const uint32_t* w = (const uint32_t*)&v[p];
#pragma unroll
        for (int e = 0; e < 4; e++) {
            float2 f = __half22float2(*(const __half2*)&w[e]);
            int base = (tid + 256 * p) * 8 + e * 2;
            if (f.x < thr) { int pos = atomicAdd(&s_cnt, 1); if (pos < 128) s_cand[pos] = base; }
            if (f.y < thr) { int pos = atomicAdd(&s_cnt, 1); if (pos < 128) s_cand[pos] = base + 1; }
        }
    }
    __syncthreads();
    int nc = min(s_cnt, 128);
    const float* zq = g_At + (size_t)q * Dd;
    for (int ci = wid; ci < nc; ci += 8) {
        int c = s_cand[ci];
        const float* cr = cb + (size_t)c * Dd;
        float s = 0.0f;
#pragma unroll
        for (int d = 0; d < Dd / 32; d++) s = fmaf(zq[lane + d * 32], cr[lane + d * 32], s);
#pragma unroll
        for (int off = 16; off; off >>= 1) s += __shfl_down_sync(0xFFFFFFFFu, s, off);
        if (lane == 0) {
            float dex = g_c2[c] - 2.0f * s;
            unsigned long long pk = ((unsigned long long)f_ord(dex) << 32) | (unsigned)c;
            atomicMin(&s_best, pk);
        }
    }
    __syncthreads();
    if (tid == 0) {
        int idx = (int)(s_best & 0xFFFFFFFFULL);
        g_idx[q] = idx;
        atomicAdd(&g_cnt[idx], 1);
    }
}

// ---------------------------------------------------------------------------
// Gather z_q to (b,d,t) + loss partials
// ---------------------------------------------------------------------------
__global__ void k_gather(const float* __restrict__ z, const float* __restrict__ cb,
                         float* __restrict__ out) {
    int bd = blockIdx.x;
    int b = bd >> 9, d = bd & 511;
    int t = threadIdx.x;
    int n = b * Tt + t;
    int idx = g_idx[n];
    size_t o = (size_t)bd * Tt + t;
    float c = cb[(size_t)idx * Dd + d];
    float zv = z[o];
    out[o] = c;
    float diff = c - zv;
    float s = diff * diff;
#pragma unroll
    for (int off = 16; off; off >>= 1) s += __shfl_down_sync(0xFFFFFFFFu, s, off);
    __shared__ float ws[8];
    if ((t & 31) == 0) ws[t >> 5] = s;
    __syncthreads();
    if (t < 8) {
        float v = ws[t];
#pragma unroll
        for (int off = 4; off; off >>= 1) v += __shfl_down_sync(0xFFu, v, off);
        if (t == 0) atomicAdd(&g_loss, v);
    }
}

// Finalize loss + perplexity
__global__ void k_final(float* __restrict__ out) {
    int t = threadIdx.x;
    float local = 0.0f;
    for (int k = t; k < Kc; k += 256) {
        float p = (float)g_cnt[k] * (1.0f / (float)Nq);
        local += p * logf(p + 1e-10f);
    }
#pragma unroll
    for (int off = 16; off; off >>= 1) local += __shfl_down_sync(0xFFFFFFFFu, local, off);
    __shared__ float ws[8];
    if ((t & 31) == 0) ws[t >> 5] = local;
    __syncthreads();
    if (t == 0) {
        float tot = 0.0f;
#pragma unroll
        for (int i = 0; i < 8; i++) tot += ws[i];
        size_t base = (size_t)Bq * Dd * Tt;
        out[base]     = 0.25f * g_loss / (float)((size_t)Nq * Dd);
        out[base + 1] = expf(-tot);
    }
}

// ---------------------------------------------------------------------------
extern "C" void kernel_launch(void* const* d_in, const int* in_sizes, int n_in,
                              void* d_out, int out_size) {
    const float* z  = (const float*)d_in[0];
    const float* cb = (const float*)d_in[1];
    float* out = (float*)d_out;
    (void)in_sizes; (void)n_in; (void)out_size;

    cudaFuncSetAttribute(k_gemm, cudaFuncAttributeMaxDynamicSharedMemorySize,
                         STAGES * STG_BYTES);

    k_init<<<32, 256>>>();
    k_norms<<<Kc / 8, 256>>>(cb);
    k_convA<<<dim3(32, 16), 256>>>(z);
    k_convB<<<Kc, 128>>>(cb);
    k_gemm<<<dim3(Nq / BM, Kc / BN), 256, STAGES * STG_BYTES>>>();
    k_scan<<<Nq, 256>>>(cb);
    k_gather<<<Bq * Dd, 256>>>(z, cb, out);
    k_final<<<1, 256>>>(out);
}

// round 5
// speedup vs baseline: 4.8285x; 1.0862x over previous
#include <cuda_runtime.h>
#include <cuda_bf16.h>
#include <cuda_fp16.h>
#include <cuda_fp8.h>
#include <cstdint>

// Problem constants
#define Bq 32
#define Dd 512
#define Tt 256
#define Nq 8192
#define Kc 8192

// GEMM tiling (fp8: BK=64 -> 64B rows, same byte layout as 32xbf16)
#define BM 128
#define BN 256
#define BK 64
#define STAGES 4
#define STG_A (BM * BK)              // 8192 B
#define STG_B (BN * BK)              // 16384 B
#define STG_BYTES (STG_A + STG_B)    // 24576 B
#define KITERS (Dd / BK)             // 8

#define MARGIN 24.0f
#define MAXCAND 512

// Scratch (device globals; no runtime allocation allowed)
__device__ unsigned char g_A8[(size_t)Nq * Dd];   // queries e4m3 [n][d]
__device__ float         g_At[(size_t)Nq * Dd];   // queries fp32 [n][d] (exact rescore)
__device__ unsigned char g_B8[(size_t)Kc * Dd];   // codebook e4m3 [c][d]
__device__ __half        g_D[(size_t)Nq * Kc];    // approx distances fp16
__device__ float         g_c2[Kc];
__device__ int           g_cnt[Kc];
__device__ int           g_idx[Nq];
__device__ float         g_loss;

// ---------------------------------------------------------------------------
// helpers
// ---------------------------------------------------------------------------
__device__ __forceinline__ uint32_t smem_u32(const void* p) {
    uint32_t a;
    asm("{ .reg .u64 t; cvta.to.shared.u64 t, %1; cvt.u32.u64 %0, t; }" : "=r"(a) : "l"(p));
    return a;
}
__device__ __forceinline__ void cp_async16(uint32_t s, const void* g) {
    asm volatile("cp.async.cg.shared.global [%0], [%1], 16;" :: "r"(s), "l"(g) : "memory");
}
#define CP_COMMIT() asm volatile("cp.async.commit_group;" ::: "memory")
#define CP_WAIT2()  asm volatile("cp.async.wait_group 2;" ::: "memory")
#define SWZ(o) ((o) ^ (((o) >> 3) & 0x70))

__device__ __forceinline__ void ldm_x4(uint32_t& r0, uint32_t& r1, uint32_t& r2, uint32_t& r3,
                                       uint32_t a) {
    asm volatile("ldmatrix.sync.aligned.m8n8.x4.shared.b16 {%0,%1,%2,%3}, [%4];"
                 : "=r"(r0), "=r"(r1), "=r"(r2), "=r"(r3) : "r"(a));
}
__device__ __forceinline__ void mma_fp8(float* c, const uint32_t* a, const uint32_t* b) {
    asm volatile(
        "mma.sync.aligned.m16n8k32.row.col.f32.e4m3.e4m3.f32 "
        "{%0,%1,%2,%3}, {%4,%5,%6,%7}, {%8,%9}, {%0,%1,%2,%3};"
        : "+f"(c[0]), "+f"(c[1]), "+f"(c[2]), "+f"(c[3])
        : "r"(a[0]), "r"(a[1]), "r"(a[2]), "r"(a[3]), "r"(b[0]), "r"(b[1]));
}
__device__ __forceinline__ unsigned f_ord(float f) {
    unsigned u = __float_as_uint(f);
    return (u & 0x80000000u) ? ~u : (u | 0x80000000u);
}
__device__ __forceinline__ uint32_t fp8x4(float a, float b, float c, float d) {
    uint32_t lo = __nv_cvt_float2_to_fp8x2(make_float2(a, b), __NV_SATFINITE, __NV_E4M3);
    uint32_t hi = __nv_cvt_float2_to_fp8x2(make_float2(c, d), __NV_SATFINITE, __NV_E4M3);
    return lo | (hi << 16);
}

// ---------------------------------------------------------------------------
// A build: transpose z (b,d,t) -> [n][d] fp32 + e4m3. grid (32,16), block 256
// ---------------------------------------------------------------------------
__global__ void k_convA(const float* __restrict__ z) {
    __shared__ float sm[32][257];
    int b = blockIdx.x, d0 = blockIdx.y * 32;
    int t = threadIdx.x;
    if (b == 0 && blockIdx.y == 0 && t == 0) g_loss = 0.0f;
    const float* zb = z + ((size_t)b * Dd + d0) * Tt;
#pragma unroll
    for (int r = 0; r < 32; r++) sm[r][t] = zb[r * Tt + t];
    __syncthreads();
    size_t row = (size_t)(b * Tt + t) * Dd + d0;
    float* pf = g_At + row;
    float v[32];
#pragma unroll
    for (int r = 0; r < 32; r++) { v[r] = sm[r][t]; pf[r] = v[r]; }
    uint32_t w[8];
#pragma unroll
    for (int q = 0; q < 8; q++)
        w[q] = fp8x4(v[4 * q], v[4 * q + 1], v[4 * q + 2], v[4 * q + 3]);
    uint4* p8 = (uint4*)(g_A8 + row);
    p8[0] = make_uint4(w[0], w[1], w[2], w[3]);
    p8[1] = make_uint4(w[4], w[5], w[6], w[7]);
}

// B build: codebook -> e4m3 + exact fp32 norms + zero cnt. grid 8192, block 128
__global__ void k_convB(const float* __restrict__ cb) {
    int c = blockIdx.x, t = threadIdx.x;
    float4 v = *(const float4*)(cb + (size_t)c * Dd + 4 * t);
    *(uint32_t*)(g_B8 + (size_t)c * Dd + 4 * t) = fp8x4(v.x, v.y, v.z, v.w);
    float s = v.x * v.x + v.y * v.y + v.z * v.z + v.w * v.w;
#pragma unroll
    for (int off = 16; off; off >>= 1) s += __shfl_down_sync(0xFFFFFFFFu, s, off);
    __shared__ float ws[4];
    if ((t & 31) == 0) ws[t >> 5] = s;
    __syncthreads();
    if (t == 0) {
        g_c2[c] = ws[0] + ws[1] + ws[2] + ws[3];
        g_cnt[c] = 0;
    }
}

// ---------------------------------------------------------------------------
// e4m3 HMMA GEMM 128x256x64, 8 warps (2x4, warp tile 64x64), 4-stage cp.async.
// Epilogue: d = ||c||^2 - 2*dot -> fp16 matrix g_D.
// grid (64, 32), block 256, dyn smem 96KB
// ---------------------------------------------------------------------------
__global__ __launch_bounds__(256, 1) void k_gemm() {
    extern __shared__ char smem[];
    const uint32_t sbase = smem_u32(smem);
    const int tid = threadIdx.x;
    const int wid = tid >> 5, lane = tid & 31;
    const int wm = (wid >> 2) * 64;
    const int wn = (wid & 3) * 64;
    const int m0 = blockIdx.x * BM, n0 = blockIdx.y * BN;

    const unsigned char* gA = g_A8;
    const unsigned char* gB = g_B8;

    float acc[4][8][4];
#pragma unroll
    for (int i = 0; i < 4; i++)
#pragma unroll
        for (int j = 0; j < 8; j++)
#pragma unroll
            for (int k = 0; k < 4; k++) acc[i][j][k] = 0.0f;

    // stage loader: rows are 64 B (BK=64 fp8)
    auto load_stage = [&](int s, int kb) {
        uint32_t sA = sbase + s * STG_BYTES;
        uint32_t sB = sA + STG_A;
#pragma unroll
        for (int p = 0; p < 2; p++) {            // A: 512 chunks of 16B
            int j = tid + 256 * p;
            int r = j >> 2, c = j & 3;
            uint32_t off = r * 64 + c * 16;
            cp_async16(sA + SWZ(off), gA + (size_t)(m0 + r) * Dd + kb + c * 16);
        }
#pragma unroll
        for (int p = 0; p < 4; p++) {            // B: 1024 chunks
            int j = tid + 256 * p;
            int r = j >> 2, c = j & 3;
            uint32_t off = r * 64 + c * 16;
            cp_async16(sB + SWZ(off), gB + (size_t)(n0 + r) * Dd + kb + c * 16);
        }
    };

    load_stage(0, 0); CP_COMMIT();
    load_stage(1, BK); CP_COMMIT();
    load_stage(2, 2 * BK); CP_COMMIT();

    for (int i = 0; i < KITERS; i++) {
        CP_WAIT2();
        __syncthreads();                 // publishes stage i, retires compute i-1
        int s = i & 3;
        if (i + 3 < KITERS) load_stage((i + 3) & 3, (i + 3) * BK);
        CP_COMMIT();

        uint32_t sA = sbase + s * STG_BYTES;
        uint32_t sB = sA + STG_A;
#pragma unroll
        for (int k32 = 0; k32 < 2; k32++) {      // two k32 steps per 64B row
            const int ch = 2 * k32 + (lane >> 4);
            uint32_t af[4][4], br[4][4];
#pragma unroll
            for (int mf = 0; mf < 4; mf++) {
                int r = wm + mf * 16 + (lane & 15);
                uint32_t off = r * 64 + ch * 16;
                ldm_x4(af[mf][0], af[mf][1], af[mf][2], af[mf][3], sA + SWZ(off));
            }
#pragma unroll
            for (int nf4 = 0; nf4 < 4; nf4++) {
                int r = wn + nf4 * 16 + (lane & 15);
                uint32_t off = r * 64 + ch * 16;
                ldm_x4(br[nf4][0], br[nf4][1], br[nf4][2], br[nf4][3], sB + SWZ(off));
            }
#pragma unroll
            for (int mf = 0; mf < 4; mf++)
#pragma unroll
                for (int nf4 = 0; nf4 < 4; nf4++) {
                    uint32_t b0[2] = {br[nf4][0], br[nf4][2]};
                    uint32_t b1[2] = {br[nf4][1], br[nf4][3]};
                    mma_fp8(acc[mf][2 * nf4],     af[mf], b0);
                    mma_fp8(acc[mf][2 * nf4 + 1], af[mf], b1);
                }
        }
    }

    // epilogue: dist = c2 - 2*dot -> fp16 store
#pragma unroll
    for (int mf = 0; mf < 4; mf++) {
#pragma unroll
        for (int nf = 0; nf < 8; nf++) {
            int m = m0 + wm + mf * 16 + (lane >> 2);
            int n = n0 + wn + nf * 8 + (lane & 3) * 2;
            float c2a = g_c2[n], c2b = g_c2[n + 1];
            float* a = acc[mf][nf];
            __half2 h0 = __float22half2_rn(make_float2(c2a - 2.0f * a[0], c2b - 2.0f * a[1]));
            __half2 h1 = __float22half2_rn(make_float2(c2a - 2.0f * a[2], c2b - 2.0f * a[3]));
            *(__half2*)(g_D + (size_t)m * Kc + n) = h0;
            *(__half2*)(g_D + (size_t)(m + 8) * Kc + n) = h1;
        }
    }
}

// ---------------------------------------------------------------------------
// Per-query scan of approx distances + exact rescore of candidates.
// grid 8192 (one block per query), block 256
// ---------------------------------------------------------------------------
__global__ __launch_bounds__(256) void k_scan(const float* __restrict__ cb) {
    const int q = blockIdx.x;
    const int tid = threadIdx.x, wid = tid >> 5, lane = tid & 31;
    const uint4* row = (const uint4*)(g_D + (size_t)q * Kc);

    uint4 v[4];
    float lmin = 3.4e38f;
#pragma unroll
    for (int p = 0; p < 4; p++) {
        v[p] = row[tid + 256 * p];
        const uint32_t* w = (const uint32_t*)&v[p];
#pragma unroll
        for (int e = 0; e < 4; e++) {
            float2 f = __half22float2(*(const __half2*)&w[e]);
            lmin = fminf(lmin, fminf(f.x, f.y));
        }
    }
    __shared__ float wmin[8];
    __shared__ float s_m;
    __shared__ int s_cnt;
    __shared__ int s_cand[MAXCAND];
    __shared__ unsigned long long s_best;
#pragma unroll
    for (int off = 16; off; off >>= 1) lmin = fminf(lmin, __shfl_down_sync(0xFFFFFFFFu, lmin, off));
    if (lane == 0) wmin[wid] = lmin;
    __syncthreads();
    if (tid == 0) {
        float m = wmin[0];
#pragma unroll
        for (int i = 1; i < 8; i++) m = fminf(m, wmin[i]);
        s_m = m; s_cnt = 0; s_best = 0xFFFFFFFFFFFFFFFFULL;
    }
    __syncthreads();
    const float thr = s_m + MARGIN;
#pragma unroll
    for (int p = 0; p < 4; p++) {
        const uint32_t* w = (const uint32_t*)&v[p];
#pragma unroll
        for (int e = 0; e < 4; e++) {
            float2 f = __half22float2(*(const __half2*)&w[e]);
            int base = (tid + 256 * p) * 8 + e * 2;
            if (f.x < thr) { int pos = atomicAdd(&s_cnt, 1); if (pos < MAXCAND) s_cand[pos] = base; }
            if (f.y < thr) { int pos = atomicAdd(&s_cnt, 1); if (pos < MAXCAND) s_cand[pos] = base + 1; }
        }
    }
    __syncthreads();
    int nc = min(s_cnt, MAXCAND);
    const float* zq = g_At + (size_t)q * Dd;
    for (int ci = wid; ci < nc; ci += 8) {
        int c = s_cand[ci];
        const float* cr = cb + (size_t)c * Dd;
        float s = 0.0f;
#pragma unroll
        for (int d = 0; d < Dd / 32; d++) s = fmaf(zq[lane + d * 32], cr[lane + d * 32], s);
#pragma unroll
        for (int off = 16; off; off >>= 1) s += __shfl_down_sync(0xFFFFFFFFu, s, off);
        if (lane == 0) {
            float dex = g_c2[c] - 2.0f * s;
            unsigned long long pk = ((unsigned long long)f_ord(dex) << 32) | (unsigned)c;
            atomicMin(&s_best, pk);
        }
    }
    __syncthreads();
    if (tid == 0) {
        int idx = (int)(s_best & 0xFFFFFFFFULL);
        g_idx[q] = idx;
        atomicAdd(&g_cnt[idx], 1);
    }
}

// ---------------------------------------------------------------------------
// Gather z_q to (b,d,t) + loss partials
// ---------------------------------------------------------------------------
__global__ void k_gather(const float* __restrict__ z, const float* __restrict__ cb,
                         float* __restrict__ out) {
    int bd = blockIdx.x;
    int b = bd >> 9, d = bd & 511;
    int t = threadIdx.x;
    int n = b * Tt + t;
    int idx = g_idx[n];
    size_t o = (size_t)bd * Tt + t;
    float c = cb[(size_t)idx * Dd + d];
    float zv = z[o];
    out[o] = c;
    float diff = c - zv;
    float s = diff * diff;
#pragma unroll
    for (int off = 16; off; off >>= 1) s += __shfl_down_sync(0xFFFFFFFFu, s, off);
    __shared__ float ws[8];
    if ((t & 31) == 0) ws[t >> 5] = s;
    __syncthreads();
    if (t < 8) {
        float v = ws[t];
#pragma unroll
        for (int off = 4; off; off >>= 1) v += __shfl_down_sync(0xFFu, v, off);
        if (t == 0) atomicAdd(&g_loss, v);
    }
}

// Finalize loss + perplexity
__global__ void k_final(float* __restrict__ out) {
    int t = threadIdx.x;
    float local = 0.0f;
    for (int k = t; k < Kc; k += 256) {
        float p = (float)g_cnt[k] * (1.0f / (float)Nq);
        local += p * logf(p + 1e-10f);
    }
#pragma unroll
    for (int off = 16; off; off >>= 1) local += __shfl_down_sync(0xFFFFFFFFu, local, off);
    __shared__ float ws[8];
    if ((t & 31) == 0) ws[t >> 5] = local;
    __syncthreads();
    if (t == 0) {
        float tot = 0.0f;
#pragma unroll
        for (int i = 0; i < 8; i++) tot += ws[i];
        size_t base = (size_t)Bq * Dd * Tt;
        out[base]     = 0.25f * g_loss / (float)((size_t)Nq * Dd);
        out[base + 1] = expf(-tot);
    }
}

// ---------------------------------------------------------------------------
extern "C" void kernel_launch(void* const* d_in, const int* in_sizes, int n_in,
                              void* d_out, int out_size) {
    const float* z  = (const float*)d_in[0];
    const float* cb = (const float*)d_in[1];
    float* out = (float*)d_out;
    (void)in_sizes; (void)n_in; (void)out_size;

    cudaFuncSetAttribute(k_gemm, cudaFuncAttributeMaxDynamicSharedMemorySize,
                         STAGES * STG_BYTES);

    k_convA<<<dim3(32, 16), 256>>>(z);
    k_convB<<<Kc, 128>>>(cb);
    k_gemm<<<dim3(Nq / BM, Kc / BN), 256, STAGES * STG_BYTES>>>();
    k_scan<<<Nq, 256>>>(cb);
    k_gather<<<Bq * Dd, 256>>>(z, cb, out);
    k_final<<<1, 256>>>(out);
}